// round 2
// baseline (speedup 1.0000x reference)
#include <cuda_runtime.h>

#define SEQ   1024
#define BATCH 512
#define NT    64

// Per-batch log-likelihoods (scratch; device global, no allocation).
__device__ float g_llh[BATCH];

__global__ void __launch_bounds__(NT)
crf_forward_kernel(const float* __restrict__ em,
                   const void* __restrict__ tags_raw,
                   const int* __restrict__ mask,
                   const float* __restrict__ startT,
                   const float* __restrict__ endT,
                   const float* __restrict__ trans)
{
    const int b    = blockIdx.x;     // one batch element per block
    const int j    = threadIdx.x;    // tag index 0..63
    const int lane = j & 31;
    const int w    = j >> 5;

    __shared__ float sh_e[2][NT];    // double-buffered exp(alpha - m)
    __shared__ float sh_red[2];      // per-warp max partials
    __shared__ float sh_num[2];      // per-warp numerator partials
    __shared__ int   sh_len[2];      // per-warp length partials
    __shared__ float sh_sum[2];      // final lse sum partials

    // ---- tags dtype detection: int64 => every odd 32-bit word is 0 ----
    // (values are 0..63; if actually int32, P(16 sampled words all zero)=64^-16)
    const int*       t32 = (const int*)tags_raw;
    const long long* t64 = (const long long*)tags_raw;
    bool is64 = true;
#pragma unroll
    for (int k = 0; k < 16; ++k)
        is64 = is64 && (t32[2 * k * 1031 + 1] == 0);   // scattered odd words

    // ---- exp(transitions) column j held in registers (time-invariant) ----
    float eT[NT];
#pragma unroll
    for (int i = 0; i < NT; ++i)
        eT[i] = __expf(trans[i * NT + j]);

    // ---- sequence length (mask is monotone: mask[t] = t < length) ----
    int cnt = 0;
    for (int t = j; t < SEQ; t += NT)
        cnt += mask[t * BATCH + b];
#pragma unroll
    for (int o = 16; o > 0; o >>= 1)
        cnt += __shfl_xor_sync(0xffffffffu, cnt, o);
    if (lane == 0) sh_len[w] = cnt;
    __syncthreads();
    const int length = sh_len[0] + sh_len[1];

    // ---- numerator partials: t in [1, length) is mask==1 territory ----
    float num = 0.f;
    if (is64) {
        for (int t = 1 + j; t < length; t += NT) {
            const int pt = (int)t64[(t - 1) * BATCH + b];
            const int ct = (int)t64[t * BATCH + b];
            num += trans[pt * NT + ct] + em[(t * BATCH + b) * NT + ct];
        }
    } else {
        for (int t = 1 + j; t < length; t += NT) {
            const int pt = t32[(t - 1) * BATCH + b];
            const int ct = t32[t * BATCH + b];
            num += trans[pt * NT + ct] + em[(t * BATCH + b) * NT + ct];
        }
    }
#pragma unroll
    for (int o = 16; o > 0; o >>= 1)
        num += __shfl_xor_sync(0xffffffffu, num, o);
    if (lane == 0) sh_num[w] = num;
    __syncthreads();

    // ---- forward recursion (normalizer) ----
    float alpha = startT[j] + em[b * NT + j];

    // distance-2 emission prefetch
    float em_p1 = (length > 1) ? em[(1 * BATCH + b) * NT + j] : 0.f;
    float em_p2 = (length > 2) ? em[(2 * BATCH + b) * NT + j] : 0.f;

    for (int t = 1; t < length; ++t) {
        const float em_t = em_p1;
        em_p1 = em_p2;
        if (t + 2 < length)
            em_p2 = em[((t + 2) * BATCH + b) * NT + j];

        // block max of alpha
        float m = alpha;
#pragma unroll
        for (int o = 16; o > 0; o >>= 1)
            m = fmaxf(m, __shfl_xor_sync(0xffffffffu, m, o));
        if (lane == 0) sh_red[w] = m;
        __syncthreads();
        m = fmaxf(sh_red[0], sh_red[1]);

        const int buf = t & 1;
        sh_e[buf][j] = __expf(alpha - m);
        __syncthreads();

        // dot(exp(alpha-m), exp(T)[:,j]) — float4 LDS, 8 accumulators
        const float4* __restrict__ e4 = (const float4*)sh_e[buf];
        float s0 = 0.f, s1 = 0.f, s2 = 0.f, s3 = 0.f;
        float s4 = 0.f, s5 = 0.f, s6 = 0.f, s7 = 0.f;
#pragma unroll
        for (int k = 0; k < NT / 8; ++k) {      // 8 iterations, 2 float4 each
            const float4 ea = e4[2 * k + 0];
            const float4 eb = e4[2 * k + 1];
            s0 = fmaf(ea.x, eT[8 * k + 0], s0);
            s1 = fmaf(ea.y, eT[8 * k + 1], s1);
            s2 = fmaf(ea.z, eT[8 * k + 2], s2);
            s3 = fmaf(ea.w, eT[8 * k + 3], s3);
            s4 = fmaf(eb.x, eT[8 * k + 4], s4);
            s5 = fmaf(eb.y, eT[8 * k + 5], s5);
            s6 = fmaf(eb.z, eT[8 * k + 6], s6);
            s7 = fmaf(eb.w, eT[8 * k + 7], s7);
        }
        const float s = ((s0 + s1) + (s2 + s3)) + ((s4 + s5) + (s6 + s7));

        alpha = m + __logf(s) + em_t;
    }

    // ---- denominator: logsumexp(alpha + end) over the 64 tags ----
    const float v = alpha + endT[j];
    float m = v;
#pragma unroll
    for (int o = 16; o > 0; o >>= 1)
        m = fmaxf(m, __shfl_xor_sync(0xffffffffu, m, o));
    if (lane == 0) sh_red[w] = m;
    __syncthreads();
    m = fmaxf(sh_red[0], sh_red[1]);

    float e = __expf(v - m);
#pragma unroll
    for (int o = 16; o > 0; o >>= 1)
        e += __shfl_xor_sync(0xffffffffu, e, o);
    if (lane == 0) sh_sum[w] = e;
    __syncthreads();

    if (j == 0) {
        const float denom = m + __logf(sh_sum[0] + sh_sum[1]);
        const int t0 = is64 ? (int)t64[b] : t32[b];
        const int tl = is64 ? (int)t64[(length - 1) * BATCH + b]
                            : t32[(length - 1) * BATCH + b];
        const float numer = sh_num[0] + sh_num[1]
                          + startT[t0] + em[b * NT + t0]
                          + endT[tl];
        g_llh[b] = numer - denom;
    }
}

// Deterministic fixed-order tree reduction (double accumulation).
__global__ void __launch_bounds__(BATCH)
crf_reduce_kernel(float* __restrict__ out)
{
    __shared__ double sh[BATCH];
    const int i = threadIdx.x;
    sh[i] = (double)g_llh[i];
    __syncthreads();
#pragma unroll
    for (int o = BATCH / 2; o > 0; o >>= 1) {
        if (i < o) sh[i] += sh[i + o];
        __syncthreads();
    }
    if (i == 0) out[0] = (float)sh[0];
}

extern "C" void kernel_launch(void* const* d_in, const int* in_sizes, int n_in,
                              void* d_out, int out_size)
{
    const float* em     = (const float*)d_in[0];
    const void*  tags   = (const void*)d_in[1];
    const int*   mask   = (const int*)d_in[2];
    const float* startT = (const float*)d_in[3];
    const float* endT   = (const float*)d_in[4];
    const float* trans  = (const float*)d_in[5];
    float* out = (float*)d_out;

    crf_forward_kernel<<<BATCH, NT>>>(em, tags, mask, startT, endT, trans);
    crf_reduce_kernel<<<1, BATCH>>>(out);
}